// round 7
// baseline (speedup 1.0000x reference)
#include <cuda_runtime.h>
#include <cuda_bf16.h>

#define IW 1024
#define IH 1024
#define NB 16
#define NC 6
#define PLANE (IW * IH)
#define FULLMASK 0xffffffffu

__device__ __forceinline__ unsigned burn4(float4 v) {
    unsigned m = 0;
    m |= (v.x > 0.5f) ? 1u : 0u;
    m |= (v.y > 0.5f) ? 2u : 0u;
    m |= (v.z > 0.5f) ? 4u : 0u;
    m |= (v.w > 0.5f) ? 8u : 0u;
    return m;
}

__global__ __launch_bounds__(256, 5)
void fire_spread_flat(const float* __restrict__ x, float* __restrict__ out) {
    const int bid = blockIdx.x;
    const int y = bid & (IH - 1);
    const int b = bid >> 10;
    const int tx = threadIdx.x;
    const int x4 = tx * 4;
    const int lane = tx & 31;

    const float* basep = x + (size_t)b * NC * PLANE;
    const size_t rowoff = (size_t)y * IW + x4;
    const float* pEC = basep + rowoff;                 // elev, row y
    const float* pFC = basep + 5 * PLANE + rowoff;     // fire, row y

    const bool vP = (y > 0);
    const bool vN = (y < IH - 1);

    const float4 z4 = make_float4(0.f, 0.f, 0.f, 0.f);

    // ---- front-batch all 10 float4 loads (max MLP) ----
    float4 ePv = vP ? *reinterpret_cast<const float4*>(pEC - IW) : z4;
    float4 eCv =      *reinterpret_cast<const float4*>(pEC);
    float4 eNv = vN ? *reinterpret_cast<const float4*>(pEC + IW) : z4;
    float4 fPv = vP ? *reinterpret_cast<const float4*>(pFC - IW) : z4;
    float4 fCv =      *reinterpret_cast<const float4*>(pFC);
    float4 fNv = vN ? *reinterpret_cast<const float4*>(pFC + IW) : z4;
    float4 ws4 = __ldcs(reinterpret_cast<const float4*>(basep + 1 * PLANE + rowoff));
    float4 wd4 = __ldcs(reinterpret_cast<const float4*>(basep + 2 * PLANE + rowoff));
    float4 hu4 = __ldcs(reinterpret_cast<const float4*>(basep + 3 * PLANE + rowoff));
    float4 nd4 = __ldcs(reinterpret_cast<const float4*>(basep + 4 * PLANE + rowoff));

    // ---- fire rows -> packed bits: [3:0]=P, [11:8]=C, [19:16]=N ----
    unsigned pk = burn4(fPv) | (burn4(fCv) << 8) | (burn4(fNv) << 16);

    // ---- halo exchange ----
    // elev: 6 scalar shuffles
    float lEP = __shfl_up_sync(FULLMASK, ePv.w, 1);
    float lEC = __shfl_up_sync(FULLMASK, eCv.w, 1);
    float lEN = __shfl_up_sync(FULLMASK, eNv.w, 1);
    float rEP = __shfl_down_sync(FULLMASK, ePv.x, 1);
    float rEC = __shfl_down_sync(FULLMASK, eCv.x, 1);
    float rEN = __shfl_down_sync(FULLMASK, eNv.x, 1);
    // fire: 2 packed shuffles
    unsigned pkL = __shfl_up_sync(FULLMASK, pk, 1);
    unsigned pkR = __shfl_down_sync(FULLMASK, pk, 1);

    if (lane == 0) {
        bool ok = (x4 > 0);
        lEP = (ok && vP) ? pEC[-IW - 1] : 0.f;
        lEC =  ok        ? pEC[-1]      : 0.f;
        lEN = (ok && vN) ? pEC[IW - 1]  : 0.f;
        unsigned m = 0;
        if (ok && vP && pFC[-IW - 1] > 0.5f) m |= 8u;
        if (ok       && pFC[-1]      > 0.5f) m |= 8u << 8;
        if (ok && vN && pFC[IW - 1]  > 0.5f) m |= 8u << 16;
        pkL = m;
    }
    if (lane == 31) {
        bool ok = (x4 + 4 < IW);
        rEP = (ok && vP) ? pEC[-IW + 4] : 0.f;
        rEC =  ok        ? pEC[4]       : 0.f;
        rEN = (ok && vN) ? pEC[IW + 4]  : 0.f;
        unsigned m = 0;
        if (ok && vP && pFC[-IW + 4] > 0.5f) m |= 1u;
        if (ok       && pFC[4]       > 0.5f) m |= 1u << 8;
        if (ok && vN && pFC[IW + 4]  > 0.5f) m |= 1u << 16;
        pkR = m;
    }

    // 6-bit row masks: bit k = column (x4-1+k)
    unsigned mP = ((pkL >> 3)  & 1u) | (((pk >> 0)  & 0xfu) << 1) | (((pkR >> 0)  & 1u) << 5);
    unsigned mC = ((pkL >> 11) & 1u) | (((pk >> 8)  & 0xfu) << 1) | (((pkR >> 8)  & 1u) << 5);
    unsigned mN = ((pkL >> 19) & 1u) | (((pk >> 16) & 0xfu) << 1) | (((pkR >> 16) & 1u) << 5);

    // elev windows
    float eP[6], eC[6], eN[6];
    eP[0]=lEP; eP[1]=ePv.x; eP[2]=ePv.y; eP[3]=ePv.z; eP[4]=ePv.w; eP[5]=rEP;
    eC[0]=lEC; eC[1]=eCv.x; eC[2]=eCv.y; eC[3]=eCv.z; eC[4]=eCv.w; eC[5]=rEC;
    eN[0]=lEN; eN[1]=eNv.x; eN[2]=eNv.y; eN[3]=eNv.z; eN[4]=eNv.w; eN[5]=rEN;

    float wsa[4] = {ws4.x, ws4.y, ws4.z, ws4.w};
    float wda[4] = {wd4.x, wd4.y, wd4.z, wd4.w};
    float hua[4] = {hu4.x, hu4.y, hu4.z, hu4.w};
    float nda[4] = {nd4.x, nd4.y, nd4.z, nd4.w};
    float fca[4] = {fCv.x, fCv.y, fCv.z, fCv.w};

    const float R = 0.70710678118654752f;
    const float DEG2RAD = 0.017453292519943295f;

    float o[4];
    #pragma unroll
    for (int j = 0; j < 4; j++) {
        // Sobel (cross-correlation, /8), zero padded
        float dxv = ((eP[j + 2] - eP[j]) + 2.0f * (eC[j + 2] - eC[j])
                    + (eN[j + 2] - eN[j])) * 0.125f;
        float dyv = ((eN[j] - eP[j]) + 2.0f * (eN[j + 1] - eP[j + 1])
                    + (eN[j + 2] - eP[j + 2])) * 0.125f;
        float v = dxv * dxv + dyv * dyv + 1e-8f;
        float g = v * rsqrtf(v);              // sqrt(v), 1 MUFU
        float slope_eff = 1.0f + 0.078f * g;  // tan(atan(g)) == g
        float md = fminf(fmaxf(1.0f - 400.0f * hua[j], 0.3f), 1.0f);
        float veg = 0.5f + 0.5f * fminf(fmaxf(nda[j], 0.0f), 1.0f);
        float base = 0.58f * slope_eff * md * veg;

        // wm = (270 - wd) deg; t = wd*pi/180 in [0, 0.01745)
        // sin(wm) = -cos t ~= t^2/2 - 1 ; cos(wm) = -sin t ~= t*(t^2/6 - 1)
        float t = wda[j] * DEG2RAD;
        float t2 = t * t;
        float sw = 0.5f * t2 - 1.0f;          // ~= -1
        float cw = t * (t2 * (1.0f / 6.0f) - 1.0f);   // ~= -t
        float c_pcs = R * (cw + sw);
        float c_mcs = R * (cw - sw);

        // Known total order for wd in [0,1) deg (descending):
        //  -sw > -c_pcs > c_mcs > -cw > cw > -c_mcs > c_pcs > sw
        // Priority select in ASCENDING order (later overrides earlier):
        float m = 0.0f;
        m = ((mP >> (j + 1)) & 1u) ?  sw     : m;   // (-1, 0)
        m = ((mP >> (j + 2)) & 1u) ?  c_pcs  : m;   // (-1, 1)
        m = ((mP >>  j     ) & 1u) ? -c_mcs  : m;   // (-1,-1)
        m = ((mC >> (j + 2)) & 1u) ?  cw     : m;   // ( 0, 1)
        m = ((mC >>  j     ) & 1u) ? -cw     : m;   // ( 0,-1)
        m = ((mN >> (j + 2)) & 1u) ?  c_mcs  : m;   // ( 1, 1)
        m = ((mN >>  j     ) & 1u) ? -c_pcs  : m;   // ( 1,-1)
        m = ((mN >> (j + 1)) & 1u) ? -sw     : m;   // ( 1, 0)

        unsigned any = (((mP | mN) >> j) & 7u) | ((mC >> j) & 5u);

        float prob = 0.0f;
        if (any) {
            float wf = 1.0f + 0.045f * m * wsa[j];
            prob = fminf(fmaxf(base * wf, 0.0f), 1.0f);
        }
        float fsv = fca[j];
        o[j] = fmaxf(fsv, (fsv < 0.5f) ? prob : 0.0f);
    }

    __stcs(reinterpret_cast<float4*>(out + (size_t)b * PLANE + rowoff),
           make_float4(o[0], o[1], o[2], o[3]));
}

extern "C" void kernel_launch(void* const* d_in, const int* in_sizes, int n_in,
                              void* d_out, int out_size) {
    (void)in_sizes; (void)n_in; (void)out_size;
    const float* x = (const float*)d_in[0];
    float* out = (float*)d_out;
    fire_spread_flat<<<NB * IH, 256>>>(x, out);
}

// round 11
// speedup vs baseline: 1.1395x; 1.1395x over previous
#include <cuda_runtime.h>
#include <cuda_bf16.h>

#define IW 1024
#define IH 1024
#define NB 16
#define NC 6
#define PLANE (IW * IH)
#define FULLMASK 0xffffffffu

__global__ __launch_bounds__(256, 4)
void fire_spread_flat(const float* __restrict__ x, float* __restrict__ out) {
    const int bid = blockIdx.x;
    const int y = bid & (IH - 1);
    const int b = bid >> 10;
    const int tx = threadIdx.x;
    const int x4 = tx * 4;
    const int lane = tx & 31;

    const float* basep = x + (size_t)b * NC * PLANE;
    const size_t rowoff = (size_t)y * IW + x4;
    const float* pEC = basep + rowoff;                 // elev, row y
    const float* pFC = basep + 5 * PLANE + rowoff;     // fire, row y

    const bool vP = (y > 0);
    const bool vN = (y < IH - 1);

    const float4 z4 = make_float4(0.f, 0.f, 0.f, 0.f);

    // ---- front-batch all 10 float4 loads (max MLP) ----
    float4 ePv = vP ? *reinterpret_cast<const float4*>(pEC - IW) : z4;
    float4 eCv =      *reinterpret_cast<const float4*>(pEC);
    float4 eNv = vN ? *reinterpret_cast<const float4*>(pEC + IW) : z4;
    float4 fPv = vP ? *reinterpret_cast<const float4*>(pFC - IW) : z4;
    float4 fCv =      *reinterpret_cast<const float4*>(pFC);
    float4 fNv = vN ? *reinterpret_cast<const float4*>(pFC + IW) : z4;
    float4 ws4 = *reinterpret_cast<const float4*>(basep + 1 * PLANE + rowoff);
    float4 wd4 = *reinterpret_cast<const float4*>(basep + 2 * PLANE + rowoff);
    float4 hu4 = *reinterpret_cast<const float4*>(basep + 3 * PLANE + rowoff);
    float4 nd4 = *reinterpret_cast<const float4*>(basep + 4 * PLANE + rowoff);

    // ---- halo scalar loads, issued NOW so they overlap the vector loads
    //      (not after the shuffles, which would serialize a 2nd round-trip) ----
    float hlEP = 0.f, hlEC = 0.f, hlEN = 0.f, hlFP = 0.f, hlFC = 0.f, hlFN = 0.f;
    float hrEP = 0.f, hrEC = 0.f, hrEN = 0.f, hrFP = 0.f, hrFC = 0.f, hrFN = 0.f;
    if (lane == 0 && x4 > 0) {
        hlEC = pEC[-1];
        hlFC = pFC[-1];
        if (vP) { hlEP = pEC[-IW - 1]; hlFP = pFC[-IW - 1]; }
        if (vN) { hlEN = pEC[ IW - 1]; hlFN = pFC[ IW - 1]; }
    }
    if (lane == 31 && x4 + 4 < IW) {
        hrEC = pEC[4];
        hrFC = pFC[4];
        if (vP) { hrEP = pEC[-IW + 4]; hrFP = pFC[-IW + 4]; }
        if (vN) { hrEN = pEC[ IW + 4]; hrFN = pFC[ IW + 4]; }
    }

    // ---- halo exchange via shuffles ----
    float lEP = __shfl_up_sync(FULLMASK, ePv.w, 1);
    float lEC = __shfl_up_sync(FULLMASK, eCv.w, 1);
    float lEN = __shfl_up_sync(FULLMASK, eNv.w, 1);
    float lFP = __shfl_up_sync(FULLMASK, fPv.w, 1);
    float lFC = __shfl_up_sync(FULLMASK, fCv.w, 1);
    float lFN = __shfl_up_sync(FULLMASK, fNv.w, 1);
    float rEP = __shfl_down_sync(FULLMASK, ePv.x, 1);
    float rEC = __shfl_down_sync(FULLMASK, eCv.x, 1);
    float rEN = __shfl_down_sync(FULLMASK, eNv.x, 1);
    float rFP = __shfl_down_sync(FULLMASK, fPv.x, 1);
    float rFC = __shfl_down_sync(FULLMASK, fCv.x, 1);
    float rFN = __shfl_down_sync(FULLMASK, fNv.x, 1);

    if (lane == 0) {
        lEP = hlEP; lEC = hlEC; lEN = hlEN;
        lFP = hlFP; lFC = hlFC; lFN = hlFN;
    }
    if (lane == 31) {
        rEP = hrEP; rEC = hrEC; rEN = hrEN;
        rFP = hrFP; rFC = hrFC; rFN = hrFN;
    }

    float eP[6], eC[6], eN[6], fP[6], fC[6], fN[6];
    eP[0]=lEP; eP[1]=ePv.x; eP[2]=ePv.y; eP[3]=ePv.z; eP[4]=ePv.w; eP[5]=rEP;
    eC[0]=lEC; eC[1]=eCv.x; eC[2]=eCv.y; eC[3]=eCv.z; eC[4]=eCv.w; eC[5]=rEC;
    eN[0]=lEN; eN[1]=eNv.x; eN[2]=eNv.y; eN[3]=eNv.z; eN[4]=eNv.w; eN[5]=rEN;
    fP[0]=lFP; fP[1]=fPv.x; fP[2]=fPv.y; fP[3]=fPv.z; fP[4]=fPv.w; fP[5]=rFP;
    fC[0]=lFC; fC[1]=fCv.x; fC[2]=fCv.y; fC[3]=fCv.z; fC[4]=fCv.w; fC[5]=rFC;
    fN[0]=lFN; fN[1]=fNv.x; fN[2]=fNv.y; fN[3]=fNv.z; fN[4]=fNv.w; fN[5]=rFN;

    float wsa[4] = {ws4.x, ws4.y, ws4.z, ws4.w};
    float wda[4] = {wd4.x, wd4.y, wd4.z, wd4.w};
    float hua[4] = {hu4.x, hu4.y, hu4.z, hu4.w};
    float nda[4] = {nd4.x, nd4.y, nd4.z, nd4.w};

    const float R = 0.70710678118654752f;
    const float DEG2RAD = 0.017453292519943295f;

    float o[4];
    #pragma unroll
    for (int j = 0; j < 4; j++) {
        // Sobel (cross-correlation, /8), zero padded
        float dxv = ((eP[j + 2] - eP[j]) + 2.0f * (eC[j + 2] - eC[j])
                    + (eN[j + 2] - eN[j])) * 0.125f;
        float dyv = ((eN[j] - eP[j]) + 2.0f * (eN[j + 1] - eP[j + 1])
                    + (eN[j + 2] - eP[j + 2])) * 0.125f;
        float v = dxv * dxv + dyv * dyv + 1e-8f;
        float g = v * rsqrtf(v);              // sqrt(v), 1 MUFU
        float slope_eff = 1.0f + 0.078f * g;  // tan(atan(g)) == g
        float md = fminf(fmaxf(1.0f - 400.0f * hua[j], 0.3f), 1.0f);
        float veg = 0.5f + 0.5f * fminf(fmaxf(nda[j], 0.0f), 1.0f);
        float base = 0.58f * slope_eff * md * veg;

        // wm = (270 - wd) deg; t = wd*pi/180 in [0, 0.01745)
        // sin(wm) = -cos t ~= t^2/2 - 1 ; cos(wm) = -sin t ~= t*(t^2/6 - 1)
        float t = wda[j] * DEG2RAD;
        float t2 = t * t;
        float sw = 0.5f * t2 - 1.0f;
        float cw = t * (t2 * (1.0f / 6.0f) - 1.0f);

        // max cos(angle_diff) over burning neighbors; -2 sentinel = none
        float m = -2.0f;
        float c_pcs = R * (cw + sw);   // 45 / 225
        float c_mcs = R * (cw - sw);   // 315 (and -c_mcs = 135)
        m = (fP[j + 1] > 0.5f) ? fmaxf(m,  sw)    : m;   // (-1, 0)  90
        m = (fP[j + 2] > 0.5f) ? fmaxf(m,  c_pcs) : m;   // (-1, 1)  45
        m = (fC[j + 2] > 0.5f) ? fmaxf(m,  cw)    : m;   // ( 0, 1)   0
        m = (fN[j + 2] > 0.5f) ? fmaxf(m,  c_mcs) : m;   // ( 1, 1) 315
        m = (fN[j + 1] > 0.5f) ? fmaxf(m, -sw)    : m;   // ( 1, 0) 270
        m = (fN[j]     > 0.5f) ? fmaxf(m, -c_pcs) : m;   // ( 1,-1) 225
        m = (fC[j]     > 0.5f) ? fmaxf(m, -cw)    : m;   // ( 0,-1) 180
        m = (fP[j]     > 0.5f) ? fmaxf(m, -c_mcs) : m;   // (-1,-1) 135

        // prob = clip(base*wf, 0, 1) — clips are provably no-ops:
        // base in (0, 0.62], wf in [0.955, 1.045] => base*wf in (0, 0.65)
        float wf = 1.0f + 0.045f * m * wsa[j];
        float prob = (m >= -1.0f) ? base * wf : 0.0f;

        float fsv = fC[j + 1];
        o[j] = fmaxf(fsv, (fsv < 0.5f) ? prob : 0.0f);
    }

    *reinterpret_cast<float4*>(out + (size_t)b * PLANE + rowoff) =
        make_float4(o[0], o[1], o[2], o[3]);
}

extern "C" void kernel_launch(void* const* d_in, const int* in_sizes, int n_in,
                              void* d_out, int out_size) {
    (void)in_sizes; (void)n_in; (void)out_size;
    const float* x = (const float*)d_in[0];
    float* out = (float*)d_out;
    fire_spread_flat<<<NB * IH, 256>>>(x, out);
}